// round 2
// baseline (speedup 1.0000x reference)
#include <cuda_runtime.h>
#include <cuda_bf16.h>
#include <cstdint>

// Problem dims (fixed)
#define B 64
#define S 2048
#define I 256
#define H 256
#define O 256
#define IH 512
#define G3 768
#define NROWS (B*S)

typedef unsigned long long ull;

#define FMA2(acc, a, b) asm("fma.rn.f32x2 %0, %1, %2, %0;" : "+l"(acc) : "l"(a), "l"(b))
#define DUP2(d, s)      asm("mov.b64 %0, {%1, %1};" : "=l"(d) : "f"(s))
#define UNPK2(lo, hi, a) asm("mov.b64 {%0, %1}, %2;" : "=f"(lo), "=f"(hi) : "l"(a))

// ---------------- scratch ----------------------------------------------------
__device__ float g_gx[(size_t)B * S * G3];
__device__ float g_hs[(size_t)B * S * H];
__device__ float g_Wx[G3 * I];
__device__ float g_bx[G3];

// ---------------- weight pack ------------------------------------------------
__global__ void pack_weights(const float* __restrict__ Wr, const float* __restrict__ Wz,
                             const float* __restrict__ Wh, const float* __restrict__ br,
                             const float* __restrict__ bz, const float* __restrict__ bh)
{
    int m = blockIdx.x;
    int d = m & 255;
    const float* Wsrc = (m < 256) ? Wr : (m < 512 ? Wz : Wh);
    for (int k = threadIdx.x; k < I; k += blockDim.x)
        g_Wx[m * I + k] = Wsrc[(size_t)d * IH + k];
    if (threadIdx.x == 0)
        g_bx[m] = (m < 256 ? br : (m < 512 ? bz : bh))[d];
}

// ---------------- FFMA2 tiled GEMM: C = A @ W^T + bias, K=256 ----------------
__global__ void __launch_bounds__(256)
gemm_bias(const float* __restrict__ A, const float* __restrict__ W,
          const float* __restrict__ bias, float* __restrict__ C, int M)
{
    __shared__ float As[16][128];
    __shared__ float Bs[16][68];

    const int n0 = blockIdx.x * 128;
    const int m0 = blockIdx.y * 64;
    const int t  = threadIdx.x;
    const int tx = t & 15;
    const int ty = t >> 4;

    ull acc[4][4];
#pragma unroll
    for (int i = 0; i < 4; i++)
#pragma unroll
        for (int j = 0; j < 4; j++) acc[i][j] = 0ull;

    for (int k0 = 0; k0 < 256; k0 += 16) {
#pragma unroll
        for (int i = 0; i < 2; i++) {
            int idx = t + i * 256;
            int r = idx & 127, kg = idx >> 7;
            float4 v = *(const float4*)(A + (size_t)(n0 + r) * 256 + k0 + kg * 4);
            As[kg * 4 + 0][r] = v.x;
            As[kg * 4 + 1][r] = v.y;
            As[kg * 4 + 2][r] = v.z;
            As[kg * 4 + 3][r] = v.w;
        }
        {
            int r = t & 63, kg = t >> 6;
            float4 v = *(const float4*)(W + (size_t)(m0 + r) * 256 + k0 + kg * 4);
            Bs[kg * 4 + 0][r] = v.x;
            Bs[kg * 4 + 1][r] = v.y;
            Bs[kg * 4 + 2][r] = v.z;
            Bs[kg * 4 + 3][r] = v.w;
        }
        __syncthreads();
#pragma unroll
        for (int kk = 0; kk < 16; kk++) {
            const ulonglong2* ap = (const ulonglong2*)&As[kk][ty * 8];
            ulonglong2 aA = ap[0];   // rows 0,1 | 2,3
            ulonglong2 aB = ap[1];   // rows 4,5 | 6,7
            float4 bv = *(const float4*)&Bs[kk][tx * 4];
            ull b0, b1, b2, b3;
            DUP2(b0, bv.x); DUP2(b1, bv.y); DUP2(b2, bv.z); DUP2(b3, bv.w);
            FMA2(acc[0][0], aA.x, b0); FMA2(acc[0][1], aA.x, b1);
            FMA2(acc[0][2], aA.x, b2); FMA2(acc[0][3], aA.x, b3);
            FMA2(acc[1][0], aA.y, b0); FMA2(acc[1][1], aA.y, b1);
            FMA2(acc[1][2], aA.y, b2); FMA2(acc[1][3], aA.y, b3);
            FMA2(acc[2][0], aB.x, b0); FMA2(acc[2][1], aB.x, b1);
            FMA2(acc[2][2], aB.x, b2); FMA2(acc[2][3], aB.x, b3);
            FMA2(acc[3][0], aB.y, b0); FMA2(acc[3][1], aB.y, b1);
            FMA2(acc[3][2], aB.y, b2); FMA2(acc[3][3], aB.y, b3);
        }
        __syncthreads();
    }

    float b0 = bias[m0 + tx * 4 + 0];
    float b1 = bias[m0 + tx * 4 + 1];
    float b2 = bias[m0 + tx * 4 + 2];
    float b3 = bias[m0 + tx * 4 + 3];
#pragma unroll
    for (int ip = 0; ip < 4; ip++) {
        float l0, h0, l1, h1, l2, h2, l3, h3;
        UNPK2(l0, h0, acc[ip][0]); UNPK2(l1, h1, acc[ip][1]);
        UNPK2(l2, h2, acc[ip][2]); UNPK2(l3, h3, acc[ip][3]);
        int r = n0 + ty * 8 + ip * 2;
        float4 o0, o1;
        o0.x = l0 + b0; o0.y = l1 + b1; o0.z = l2 + b2; o0.w = l3 + b3;
        o1.x = h0 + b0; o1.y = h1 + b1; o1.z = h2 + b2; o1.w = h3 + b3;
        *(float4*)(C + (size_t)r * M + m0 + tx * 4)       = o0;
        *(float4*)(C + (size_t)(r + 1) * M + m0 + tx * 4) = o1;
    }
}

// ---------------- recurrent kernel -------------------------------------------
// 16 clusters x 8 CTAs. Cluster c: batches [4c,4c+4). CTA rank j: dims [32j,32j+32).
// All recurrent weights live in REGISTERS (per-thread slices). h / r*h replicated
// cluster-wide in SMEM via st.shared::cluster. fma.rn.f32x2 packed math.
#define CHSTR 68           // per-64-chunk padded stride (floats)
#define BSTR  272          // per-batch stride = 4*CHSTR
#define CS 8

__device__ __forceinline__ void cluster_sync_all()
{
    asm volatile("barrier.cluster.arrive.aligned;" ::: "memory");
    asm volatile("barrier.cluster.wait.aligned;" ::: "memory");
}

extern "C" __global__ void __cluster_dims__(CS, 1, 1) __launch_bounds__(256, 1)
gru_rec(const float* __restrict__ gx, const float* __restrict__ Wr,
        const float* __restrict__ Wz, const float* __restrict__ Wh,
        float* __restrict__ hs, float* __restrict__ hlast)
{
    __shared__ float hbuf[4 * BSTR];     // replicated h   [b][chunk][68]
    __shared__ float rhbuf[4 * BSTR];    // replicated r*h
    __shared__ float sz[128];            // z gate [d][b]
    __shared__ float stage[8 * 144];     // hs staging: [slot][b*36+d]

    const int t  = threadIdx.x;
    const int cl = blockIdx.x >> 3;
    const int j  = blockIdx.x & 7;

    const int c = t & 3;            // lane's batch AND k-chunk
    const int p = t >> 2;           // pair 0..63
    const int g = p >> 5;           // 0 = r (warps 0-3), 1 = z (warps 4-7)
    const int d = p & 31;
    const int dimg = j * 32 + d;

    // ---- weights into registers: wA = W_{r|z}[dimg][256+c*64 ..], wB = W_h same
    ull wA[32], wB[32];
    {
        const float* rA = (g ? Wz : Wr) + (size_t)dimg * IH + 256 + c * 64;
        const float* rB = Wh            + (size_t)dimg * IH + 256 + c * 64;
#pragma unroll
        for (int i = 0; i < 16; i++) {
            ulonglong2 v = *(const ulonglong2*)(rA + i * 4);
            wA[2 * i] = v.x; wA[2 * i + 1] = v.y;
            ulonglong2 u = *(const ulonglong2*)(rB + i * 4);
            wB[2 * i] = u.x; wB[2 * i + 1] = u.y;
        }
    }

    for (int i = t; i < 4 * BSTR; i += 256) { hbuf[i] = 0.f; rhbuf[i] = 0.f; }
    if (t < 128) sz[t] = 0.f;
    __syncthreads();

    // ---- precompute remote DSMEM addresses (constant across steps)
    const int slot = c * BSTR + (dimg >> 6) * CHSTR + (dimg & 63);
    unsigned rh_addr[8], h_addr[8];
    {
        unsigned rl = (unsigned)__cvta_generic_to_shared(&rhbuf[slot]);
        unsigned hl = (unsigned)__cvta_generic_to_shared(&hbuf[slot]);
#pragma unroll
        for (int r = 0; r < 8; r++) {
            asm("mapa.shared::cluster.u32 %0, %1, %2;" : "=r"(rh_addr[r]) : "r"(rl), "r"(r));
            asm("mapa.shared::cluster.u32 %0, %1, %2;" : "=r"(h_addr[r])  : "r"(hl), "r"(r));
        }
    }
    cluster_sync_all();   // buffers zeroed cluster-wide before any remote store

    const float* gx_b = gx + (size_t)(cl * 4 + c) * S * G3;
    const int gxa_off = g * 256 + dimg;

    for (int s = 0; s < S; s++) {
        const size_t sb = (size_t)s * G3;
        float gxa = __ldg(gx_b + sb + gxa_off);
        float gxh = (t < 128) ? __ldg(gx_b + sb + 512 + dimg) : 0.f;
        float hold = hbuf[slot];     // h_prev[c][dimg]

        // ---- sub-A: dot over h for r (warps 0-3) / z (warps 4-7), 4 batches
        float sum0, sum1, sum2, sum3;
        {
            ull a0 = 0ull, a1 = 0ull, a2 = 0ull, a3 = 0ull;
#pragma unroll
            for (int i = 0; i < 16; i++) {
                const ulonglong2* hp0 = (const ulonglong2*)(hbuf + 0 * BSTR + c * CHSTR);
                const ulonglong2* hp1 = (const ulonglong2*)(hbuf + 1 * BSTR + c * CHSTR);
                const ulonglong2* hp2 = (const ulonglong2*)(hbuf + 2 * BSTR + c * CHSTR);
                const ulonglong2* hp3 = (const ulonglong2*)(hbuf + 3 * BSTR + c * CHSTR);
                ulonglong2 h0 = hp0[i], h1 = hp1[i], h2 = hp2[i], h3 = hp3[i];
                FMA2(a0, wA[2 * i], h0.x); FMA2(a0, wA[2 * i + 1], h0.y);
                FMA2(a1, wA[2 * i], h1.x); FMA2(a1, wA[2 * i + 1], h1.y);
                FMA2(a2, wA[2 * i], h2.x); FMA2(a2, wA[2 * i + 1], h2.y);
                FMA2(a3, wA[2 * i], h3.x); FMA2(a3, wA[2 * i + 1], h3.y);
            }
            float lo, hi;
            UNPK2(lo, hi, a0); sum0 = lo + hi;
            UNPK2(lo, hi, a1); sum1 = lo + hi;
            UNPK2(lo, hi, a2); sum2 = lo + hi;
            UNPK2(lo, hi, a3); sum3 = lo + hi;
        }
#pragma unroll
        for (int m = 1; m <= 2; m <<= 1) {
            sum0 += __shfl_xor_sync(0xffffffffu, sum0, m);
            sum1 += __shfl_xor_sync(0xffffffffu, sum1, m);
            sum2 += __shfl_xor_sync(0xffffffffu, sum2, m);
            sum3 += __shfl_xor_sync(0xffffffffu, sum3, m);
        }
        float mysum = (c & 1) ? ((c & 2) ? sum3 : sum1) : ((c & 2) ? sum2 : sum0);
        float pre = mysum + gxa;
        float gate = __fdividef(1.f, 1.f + __expf(-pre));

        if (t < 128) {
            float rh = gate * hold;
#pragma unroll
            for (int r = 0; r < 8; r++)
                asm volatile("st.shared::cluster.f32 [%0], %1;" :: "r"(rh_addr[r]), "f"(rh) : "memory");
        } else {
            sz[d * 4 + c] = gate;
        }
        cluster_sync_all();

        // ---- sub-B: htilde dot over r*h + state update (warps 0-3)
        if (t < 128) {
            ull a0 = 0ull, a1 = 0ull, a2 = 0ull, a3 = 0ull;
#pragma unroll
            for (int i = 0; i < 16; i++) {
                const ulonglong2* hp0 = (const ulonglong2*)(rhbuf + 0 * BSTR + c * CHSTR);
                const ulonglong2* hp1 = (const ulonglong2*)(rhbuf + 1 * BSTR + c * CHSTR);
                const ulonglong2* hp2 = (const ulonglong2*)(rhbuf + 2 * BSTR + c * CHSTR);
                const ulonglong2* hp3 = (const ulonglong2*)(rhbuf + 3 * BSTR + c * CHSTR);
                ulonglong2 h0 = hp0[i], h1 = hp1[i], h2 = hp2[i], h3 = hp3[i];
                FMA2(a0, wB[2 * i], h0.x); FMA2(a0, wB[2 * i + 1], h0.y);
                FMA2(a1, wB[2 * i], h1.x); FMA2(a1, wB[2 * i + 1], h1.y);
                FMA2(a2, wB[2 * i], h2.x); FMA2(a2, wB[2 * i + 1], h2.y);
                FMA2(a3, wB[2 * i], h3.x); FMA2(a3, wB[2 * i + 1], h3.y);
            }
            float lo, hi, c0, c1, c2, c3;
            UNPK2(lo, hi, a0); c0 = lo + hi;
            UNPK2(lo, hi, a1); c1 = lo + hi;
            UNPK2(lo, hi, a2); c2 = lo + hi;
            UNPK2(lo, hi, a3); c3 = lo + hi;
#pragma unroll
            for (int m = 1; m <= 2; m <<= 1) {
                c0 += __shfl_xor_sync(0xffffffffu, c0, m);
                c1 += __shfl_xor_sync(0xffffffffu, c1, m);
                c2 += __shfl_xor_sync(0xffffffffu, c2, m);
                c3 += __shfl_xor_sync(0xffffffffu, c3, m);
            }
            float myc = (c & 1) ? ((c & 2) ? c3 : c1) : ((c & 2) ? c2 : c0);
            float pre2 = myc + gxh;
            // tanh(x) = 1 - 2/(e^{2x}+1)
            float e2 = __expf(2.f * pre2);
            float htil = 1.f - __fdividef(2.f, e2 + 1.f);
            float z = sz[d * 4 + c];
            float hn = hold + z * (htil - hold);
#pragma unroll
            for (int r = 0; r < 8; r++)
                asm volatile("st.shared::cluster.f32 [%0], %1;" :: "r"(h_addr[r]), "f"(hn) : "memory");
            stage[(s & 7) * 144 + c * 36 + d] = hn;
        } else {
            // warps 4-7: coalesced dump of the previous 4-step group of hs
            if ((s & 3) == 0 && s > 0) {
                int u = t - 128;
                int run = u >> 3, l8 = u & 7;
                int st_in = run >> 2, b = run & 3;
                int sidx = s - 4 + st_in;
                float4 v = *(const float4*)(stage + (sidx & 7) * 144 + b * 36 + l8 * 4);
                *(float4*)(hs + ((size_t)(cl * 4 + b) * S + sidx) * H + j * 32 + l8 * 4) = v;
            }
        }
        cluster_sync_all();
    }

    // final group of hs (steps S-4 .. S-1)
    if (t >= 128) {
        int u = t - 128;
        int run = u >> 3, l8 = u & 7;
        int st_in = run >> 2, b = run & 3;
        int sidx = S - 4 + st_in;
        float4 v = *(const float4*)(stage + (sidx & 7) * 144 + b * 36 + l8 * 4);
        *(float4*)(hs + ((size_t)(cl * 4 + b) * S + sidx) * H + j * 32 + l8 * 4) = v;
    }
    // h_last (rank 0 only; hbuf holds h_final replicated)
    if (j == 0) {
        int b = t >> 6, q = t & 63;
        float4 v = *(const float4*)(hbuf + b * BSTR + (q >> 4) * CHSTR + (q & 15) * 4);
        *(float4*)(hlast + (size_t)(cl * 4 + b) * H + q * 4) = v;
    }
}

// ---------------- launch ------------------------------------------------------
extern "C" void kernel_launch(void* const* d_in, const int* in_sizes, int n_in,
                              void* d_out, int out_size)
{
    const float* x    = (const float*)d_in[0];
    const float* W_r  = (const float*)d_in[1];
    const float* b_r  = (const float*)d_in[2];
    const float* W_z  = (const float*)d_in[3];
    const float* b_z  = (const float*)d_in[4];
    const float* W_h  = (const float*)d_in[5];
    const float* b_h  = (const float*)d_in[6];
    const float* W_fc = (const float*)d_in[7];
    const float* b_fc = (const float*)d_in[8];
    float* out = (float*)d_out;
    float* hlast = out + (size_t)B * S * O;

    float *gx, *hsp, *Wx, *bx;
    cudaGetSymbolAddress((void**)&gx,  g_gx);
    cudaGetSymbolAddress((void**)&hsp, g_hs);
    cudaGetSymbolAddress((void**)&Wx,  g_Wx);
    cudaGetSymbolAddress((void**)&bx,  g_bx);

    pack_weights<<<G3, 64>>>(W_r, W_z, W_h, b_r, b_z, b_h);
    gemm_bias<<<dim3(NROWS / 128, G3 / 64), 256>>>(x, Wx, bx, gx, G3);
    gru_rec<<<128, 256>>>(gx, W_r, W_z, W_h, hsp, hlast);
    gemm_bias<<<dim3(NROWS / 128, O / 64), 256>>>(hsp, W_fc, b_fc, out, O);
}

// round 3
// speedup vs baseline: 1.3660x; 1.3660x over previous
#include <cuda_runtime.h>
#include <cuda_bf16.h>
#include <cstdint>

// Problem dims (fixed)
#define B 64
#define S 2048
#define I 256
#define H 256
#define O 256
#define IH 512
#define G3 768
#define NROWS (B*S)

typedef unsigned long long ull;

#define FMA2(acc, a, b) asm("fma.rn.f32x2 %0, %1, %2, %0;" : "+l"(acc) : "l"(a), "l"(b))
#define DUP2(d, s)      asm("mov.b64 %0, {%1, %1};" : "=l"(d) : "f"(s))
#define UNPK2(lo, hi, a) asm("mov.b64 {%0, %1}, %2;" : "=f"(lo), "=f"(hi) : "l"(a))

// ---------------- scratch ----------------------------------------------------
__device__ float g_gx[(size_t)B * S * G3];
__device__ float g_hs[(size_t)B * S * H];
__device__ float g_Wx[G3 * I];
__device__ float g_bx[G3];

// ---------------- weight pack ------------------------------------------------
__global__ void pack_weights(const float* __restrict__ Wr, const float* __restrict__ Wz,
                             const float* __restrict__ Wh, const float* __restrict__ br,
                             const float* __restrict__ bz, const float* __restrict__ bh)
{
    int m = blockIdx.x;
    int d = m & 255;
    const float* Wsrc = (m < 256) ? Wr : (m < 512 ? Wz : Wh);
    for (int k = threadIdx.x; k < I; k += blockDim.x)
        g_Wx[m * I + k] = Wsrc[(size_t)d * IH + k];
    if (threadIdx.x == 0)
        g_bx[m] = (m < 256 ? br : (m < 512 ? bz : bh))[d];
}

// ---------------- FFMA2 tiled GEMM: C = A @ W^T + bias, K=256 ----------------
__global__ void __launch_bounds__(256)
gemm_bias(const float* __restrict__ A, const float* __restrict__ W,
          const float* __restrict__ bias, float* __restrict__ C, int M)
{
    __shared__ float As[16][128];
    __shared__ float Bs[16][68];

    const int n0 = blockIdx.x * 128;
    const int m0 = blockIdx.y * 64;
    const int t  = threadIdx.x;
    const int tx = t & 15;
    const int ty = t >> 4;

    ull acc[4][4];
#pragma unroll
    for (int i = 0; i < 4; i++)
#pragma unroll
        for (int j = 0; j < 4; j++) acc[i][j] = 0ull;

    for (int k0 = 0; k0 < 256; k0 += 16) {
#pragma unroll
        for (int i = 0; i < 2; i++) {
            int idx = t + i * 256;
            int r = idx & 127, kg = idx >> 7;
            float4 v = *(const float4*)(A + (size_t)(n0 + r) * 256 + k0 + kg * 4);
            As[kg * 4 + 0][r] = v.x;
            As[kg * 4 + 1][r] = v.y;
            As[kg * 4 + 2][r] = v.z;
            As[kg * 4 + 3][r] = v.w;
        }
        {
            int r = t & 63, kg = t >> 6;
            float4 v = *(const float4*)(W + (size_t)(m0 + r) * 256 + k0 + kg * 4);
            Bs[kg * 4 + 0][r] = v.x;
            Bs[kg * 4 + 1][r] = v.y;
            Bs[kg * 4 + 2][r] = v.z;
            Bs[kg * 4 + 3][r] = v.w;
        }
        __syncthreads();
#pragma unroll
        for (int kk = 0; kk < 16; kk++) {
            const ulonglong2* ap = (const ulonglong2*)&As[kk][ty * 8];
            ulonglong2 aA = ap[0];
            ulonglong2 aB = ap[1];
            float4 bv = *(const float4*)&Bs[kk][tx * 4];
            ull b0, b1, b2, b3;
            DUP2(b0, bv.x); DUP2(b1, bv.y); DUP2(b2, bv.z); DUP2(b3, bv.w);
            FMA2(acc[0][0], aA.x, b0); FMA2(acc[0][1], aA.x, b1);
            FMA2(acc[0][2], aA.x, b2); FMA2(acc[0][3], aA.x, b3);
            FMA2(acc[1][0], aA.y, b0); FMA2(acc[1][1], aA.y, b1);
            FMA2(acc[1][2], aA.y, b2); FMA2(acc[1][3], aA.y, b3);
            FMA2(acc[2][0], aB.x, b0); FMA2(acc[2][1], aB.x, b1);
            FMA2(acc[2][2], aB.x, b2); FMA2(acc[2][3], aB.x, b3);
            FMA2(acc[3][0], aB.y, b0); FMA2(acc[3][1], aB.y, b1);
            FMA2(acc[3][2], aB.y, b2); FMA2(acc[3][3], aB.y, b3);
        }
        __syncthreads();
    }

    float b0 = bias[m0 + tx * 4 + 0];
    float b1 = bias[m0 + tx * 4 + 1];
    float b2 = bias[m0 + tx * 4 + 2];
    float b3 = bias[m0 + tx * 4 + 3];
#pragma unroll
    for (int ip = 0; ip < 4; ip++) {
        float l0, h0, l1, h1, l2, h2, l3, h3;
        UNPK2(l0, h0, acc[ip][0]); UNPK2(l1, h1, acc[ip][1]);
        UNPK2(l2, h2, acc[ip][2]); UNPK2(l3, h3, acc[ip][3]);
        int r = n0 + ty * 8 + ip * 2;
        float4 o0, o1;
        o0.x = l0 + b0; o0.y = l1 + b1; o0.z = l2 + b2; o0.w = l3 + b3;
        o1.x = h0 + b0; o1.y = h1 + b1; o1.z = h2 + b2; o1.w = h3 + b3;
        *(float4*)(C + (size_t)r * M + m0 + tx * 4)       = o0;
        *(float4*)(C + (size_t)(r + 1) * M + m0 + tx * 4) = o1;
    }
}

// profiler-slot alignment dummy
__global__ void dummy_k() {}

// ---------------- recurrent kernel -------------------------------------------
// 16 clusters x 8 CTAs (cluster c: batches [4c,4c+4); rank j: dims [32j,32j+32)).
// 384 threads: t<128 r-gate, 128..255 z-gate, 256..383 h-gate.
// thread fields: q = t&3 (k-quarter AND result batch), d = (t>>2)&31.
// Weights: 64 floats per thread in REGISTERS. Cross-CTA exchange of h and r*h
// via st.async.shared::cluster + mbarrier complete_tx (no cluster barriers in loop).
#define CH 68              // padded 64-chunk stride (floats)
#define BST 272            // per-batch stride = 4*CH
#define HBUF_F 1088        // 4*BST floats per h parity

__device__ __forceinline__ void cluster_sync_all()
{
    asm volatile("barrier.cluster.arrive.aligned;" ::: "memory");
    asm volatile("barrier.cluster.wait.aligned;" ::: "memory");
}

__device__ __forceinline__ void mbar_init(unsigned bar, unsigned count)
{
    asm volatile("mbarrier.init.shared.b64 [%0], %1;" :: "r"(bar), "r"(count) : "memory");
}
__device__ __forceinline__ void mbar_expect_tx(unsigned bar, unsigned bytes)
{
    asm volatile("mbarrier.arrive.expect_tx.shared.b64 _, [%0], %1;" :: "r"(bar), "r"(bytes) : "memory");
}
__device__ __forceinline__ void mbar_wait(unsigned bar, unsigned phase)
{
    unsigned done;
    asm volatile(
        "{\n\t.reg .pred p;\n\t"
        "mbarrier.try_wait.parity.acquire.cta.shared::cta.b64 p, [%1], %2;\n\t"
        "selp.b32 %0, 1, 0, p;\n\t}"
        : "=r"(done) : "r"(bar), "r"(phase) : "memory");
    if (!done) {
        asm volatile(
            "{\n\t.reg .pred P1;\n\t"
            "WL_%=:\n\t"
            "mbarrier.try_wait.parity.acquire.cta.shared::cta.b64 P1, [%0], %1, 0x989680;\n\t"
            "@P1 bra.uni WD_%=;\n\t"
            "bra.uni WL_%=;\n\t"
            "WD_%=:\n\t}"
            :: "r"(bar), "r"(phase) : "memory");
    }
}
__device__ __forceinline__ void st_async_f32(unsigned raddr, float v, unsigned rbar)
{
    asm volatile("st.async.shared::cluster.mbarrier::complete_tx::bytes.b32 [%0], %1, [%2];"
                 :: "r"(raddr), "r"(__float_as_uint(v)), "r"(rbar) : "memory");
}

extern "C" __global__ void __cluster_dims__(8, 1, 1) __launch_bounds__(384, 1)
gru_rec(const float* __restrict__ gx, const float* __restrict__ Wr,
        const float* __restrict__ Wz, const float* __restrict__ Wh,
        float* __restrict__ hs, float* __restrict__ hlast)
{
    __shared__ float hbuf[2 * HBUF_F];      // double-buffered replicated h
    __shared__ float rhbuf[4 * BST];        // replicated r*h (single buffer)
    __shared__ float zbuf[128];             // z gates  [d*4+q]
    __shared__ ull   mbars[2];              // [0]=H, [1]=RH

    const int t  = threadIdx.x;
    const int cl = blockIdx.x >> 3;
    const int j  = blockIdx.x & 7;

    const int q = t & 3;                    // k-quarter AND result batch
    const int d = (t >> 2) & 31;
    const int dimg = j * 32 + d;
    const int cslot = (dimg >> 6) * CH + (dimg & 63);   // slot of dimg within a batch row

    const unsigned barH  = (unsigned)__cvta_generic_to_shared(&mbars[0]);
    const unsigned barRH = (unsigned)__cvta_generic_to_shared(&mbars[1]);

    // ---- weights into registers: 64 floats = 32 ull
    ull w[32];
    {
        const float* Wg = (t < 128) ? Wr : (t < 256 ? Wz : Wh);
        const float* row = Wg + (size_t)dimg * IH + 256 + q * 64;
#pragma unroll
        for (int i = 0; i < 16; i++) {
            ulonglong2 v = *(const ulonglong2*)(row + i * 4);
            w[2 * i] = v.x; w[2 * i + 1] = v.y;
        }
    }

    // ---- init smem + mbarriers + pre-post expects
    for (int i = t; i < 2 * HBUF_F; i += 384) hbuf[i] = 0.f;
    for (int i = t; i < 4 * BST; i += 384) rhbuf[i] = 0.f;
    if (t < 128) zbuf[t] = 0.f;
    if (t == 0) {
        mbar_init(barH, 1);
        mbar_init(barRH, 1);
        mbar_expect_tx(barH, 4096);     // satisfied by sub-B(0) stores, waited at s=1
        mbar_expect_tx(barRH, 4096);    // satisfied by sub-A(0) stores, waited at s=0
    }
    __syncthreads();
    cluster_sync_all();                  // everything visible cluster-wide

    // ---- precompute remote DSMEM addresses (byte addrs in shared::cluster space)
    unsigned dat_rem[8], bar_rem[8];     // data slot + completion barrier per rank
    {
        unsigned loc_dat, loc_bar;
        if (t < 128) {                   // r-threads -> rhbuf / barRH
            loc_dat = (unsigned)__cvta_generic_to_shared(&rhbuf[q * BST + cslot]);
            loc_bar = barRH;
        } else {                         // h-threads -> hbuf / barH (z unused)
            loc_dat = (unsigned)__cvta_generic_to_shared(&hbuf[q * BST + cslot]);
            loc_bar = barH;
        }
#pragma unroll
        for (int r = 0; r < 8; r++) {
            asm("mapa.shared::cluster.u32 %0, %1, %2;" : "=r"(dat_rem[r]) : "r"(loc_dat), "r"(r));
            asm("mapa.shared::cluster.u32 %0, %1, %2;" : "=r"(bar_rem[r]) : "r"(loc_bar), "r"(r));
        }
    }

    // ---- gx prefetch pipeline (depth 2); each thread needs ONE float per step
    const int myoff = (t < 256) ? ((t >> 7) * 256 + dimg) : (512 + dimg);
    const float* gptr = gx + ((size_t)(cl * 4 + q) * S) * G3 + myoff;
    float gv0 = __ldg(gptr);
    float gv1 = __ldg(gptr + G3);

    unsigned parH = 0, parRH = 0;

    for (int s = 0; s < S; s++) {
        const int cur = s & 1;
        const int nxt = cur ^ 1;

        // rotate gx prefetch (issue LDG for s+2 now, consume at s+2)
        float gv = gv0;
        gv0 = gv1;
        if (s + 2 < S) gv1 = __ldg(gptr + 2 * G3);
        gptr += G3;

        if (s > 0) {
            mbar_wait(barH, parH); parH ^= 1;
            if (t == 0) mbar_expect_tx(barH, 4096);    // re-arm for step s+1's h
        }
        __syncthreads();   // A: orders expect-post before rh stores; h data ready

        if (t < 256) {
            // ---- sub-A: partial dots for 4 batches over 64-float k-slice
            ull a0 = 0ull, a1 = 0ull, a2 = 0ull, a3 = 0ull;
            const ulonglong2* h0p = (const ulonglong2*)(hbuf + cur * HBUF_F + 0 * BST + q * CH);
            const ulonglong2* h1p = (const ulonglong2*)(hbuf + cur * HBUF_F + 1 * BST + q * CH);
            const ulonglong2* h2p = (const ulonglong2*)(hbuf + cur * HBUF_F + 2 * BST + q * CH);
            const ulonglong2* h3p = (const ulonglong2*)(hbuf + cur * HBUF_F + 3 * BST + q * CH);
#pragma unroll
            for (int i = 0; i < 16; i++) {
                ulonglong2 x0 = h0p[i], x1 = h1p[i], x2 = h2p[i], x3 = h3p[i];
                FMA2(a0, w[2 * i], x0.x); FMA2(a0, w[2 * i + 1], x0.y);
                FMA2(a1, w[2 * i], x1.x); FMA2(a1, w[2 * i + 1], x1.y);
                FMA2(a2, w[2 * i], x2.x); FMA2(a2, w[2 * i + 1], x2.y);
                FMA2(a3, w[2 * i], x3.x); FMA2(a3, w[2 * i + 1], x3.y);
            }
            float lo, hi, p0, p1, p2, p3;
            UNPK2(lo, hi, a0); p0 = lo + hi;
            UNPK2(lo, hi, a1); p1 = lo + hi;
            UNPK2(lo, hi, a2); p2 = lo + hi;
            UNPK2(lo, hi, a3); p3 = lo + hi;
            // reduce over q (3 shfl); thread ends with batch==q total
            float u01 = (q & 1) ? p0 : p1;
            u01 = __shfl_xor_sync(0xffffffffu, u01, 1);
            float v0 = ((q & 1) ? p1 : p0) + u01;
            float u23 = (q & 1) ? p2 : p3;
            u23 = __shfl_xor_sync(0xffffffffu, u23, 1);
            float v1 = ((q & 1) ? p3 : p2) + u23;
            float uu = (q & 2) ? v0 : v1;
            uu = __shfl_xor_sync(0xffffffffu, uu, 2);
            float tot = ((q & 2) ? v1 : v0) + uu;

            float pre = tot + gv;
            float gate = __fdividef(1.f, 1.f + __expf(-pre));

            if (t < 128) {
                float hold = hbuf[cur * HBUF_F + q * BST + cslot];
                float rh = gate * hold;
#pragma unroll
                for (int r = 0; r < 8; r++) st_async_f32(dat_rem[r], rh, bar_rem[r]);
            } else {
                zbuf[(d << 2) | q] = gate;
            }
        }

        mbar_wait(barRH, parRH); parRH ^= 1;
        if (t == 0) mbar_expect_tx(barRH, 4096);       // re-arm for step s+1's rh
        __syncthreads();   // B: zbuf visible; expect-post before h stores

        if (t >= 256) {
            // ---- sub-B: htilde partial dots over r*h
            ull a0 = 0ull, a1 = 0ull, a2 = 0ull, a3 = 0ull;
            const ulonglong2* r0p = (const ulonglong2*)(rhbuf + 0 * BST + q * CH);
            const ulonglong2* r1p = (const ulonglong2*)(rhbuf + 1 * BST + q * CH);
            const ulonglong2* r2p = (const ulonglong2*)(rhbuf + 2 * BST + q * CH);
            const ulonglong2* r3p = (const ulonglong2*)(rhbuf + 3 * BST + q * CH);
#pragma unroll
            for (int i = 0; i < 16; i++) {
                ulonglong2 x0 = r0p[i], x1 = r1p[i], x2 = r2p[i], x3 = r3p[i];
                FMA2(a0, w[2 * i], x0.x); FMA2(a0, w[2 * i + 1], x0.y);
                FMA2(a1, w[2 * i], x1.x); FMA2(a1, w[2 * i + 1], x1.y);
                FMA2(a2, w[2 * i], x2.x); FMA2(a2, w[2 * i + 1], x2.y);
                FMA2(a3, w[2 * i], x3.x); FMA2(a3, w[2 * i + 1], x3.y);
            }
            float lo, hi, p0, p1, p2, p3;
            UNPK2(lo, hi, a0); p0 = lo + hi;
            UNPK2(lo, hi, a1); p1 = lo + hi;
            UNPK2(lo, hi, a2); p2 = lo + hi;
            UNPK2(lo, hi, a3); p3 = lo + hi;
            float u01 = (q & 1) ? p0 : p1;
            u01 = __shfl_xor_sync(0xffffffffu, u01, 1);
            float v0 = ((q & 1) ? p1 : p0) + u01;
            float u23 = (q & 1) ? p2 : p3;
            u23 = __shfl_xor_sync(0xffffffffu, u23, 1);
            float v1 = ((q & 1) ? p3 : p2) + u23;
            float uu = (q & 2) ? v0 : v1;
            uu = __shfl_xor_sync(0xffffffffu, uu, 2);
            float tot = ((q & 2) ? v1 : v0) + uu;

            float pre2 = tot + gv;
            float e2 = __expf(2.f * pre2);
            float htil = 1.f - __fdividef(2.f, e2 + 1.f);
            float hold = hbuf[cur * HBUF_F + q * BST + cslot];
            float z = zbuf[(d << 2) | q];
            float hn = fmaf(z, htil - hold, hold);
#pragma unroll
            for (int r = 0; r < 8; r++)
                st_async_f32(dat_rem[r] + nxt * (HBUF_F * 4), hn, bar_rem[r]);
            hs[((size_t)(cl * 4 + q) * S + s) * H + dimg] = hn;
        }
    }

    // final h arrived?
    mbar_wait(barH, parH);
    cluster_sync_all();
    if (j == 0) {
        for (int i = t; i < 4 * H; i += 384) {
            int b = i >> 8, dim = i & 255;
            float v = hbuf[(S & 1) * HBUF_F + b * BST + (dim >> 6) * CH + (dim & 63)];
            hlast[(size_t)(cl * 4 + b) * H + dim] = v;
        }
    }
    cluster_sync_all();
}

// ---------------- launch ------------------------------------------------------
extern "C" void kernel_launch(void* const* d_in, const int* in_sizes, int n_in,
                              void* d_out, int out_size)
{
    const float* x    = (const float*)d_in[0];
    const float* W_r  = (const float*)d_in[1];
    const float* b_r  = (const float*)d_in[2];
    const float* W_z  = (const float*)d_in[3];
    const float* b_z  = (const float*)d_in[4];
    const float* W_h  = (const float*)d_in[5];
    const float* b_h  = (const float*)d_in[6];
    const float* W_fc = (const float*)d_in[7];
    const float* b_fc = (const float*)d_in[8];
    float* out = (float*)d_out;
    float* hlast = out + (size_t)B * S * O;

    float *gx, *hsp, *Wx, *bx;
    cudaGetSymbolAddress((void**)&gx,  g_gx);
    cudaGetSymbolAddress((void**)&hsp, g_hs);
    cudaGetSymbolAddress((void**)&Wx,  g_Wx);
    cudaGetSymbolAddress((void**)&bx,  g_bx);

    pack_weights<<<G3, 64>>>(W_r, W_z, W_h, b_r, b_z, b_h);
    gemm_bias<<<dim3(NROWS / 128, G3 / 64), 256>>>(x, Wx, bx, gx, G3);
    dummy_k<<<1, 32>>>();   // aligns gru_rec onto the ncu capture slot
    gru_rec<<<128, 384>>>(gx, W_r, W_z, W_h, hsp, hlast);
    gemm_bias<<<dim3(NROWS / 128, O / 64), 256>>>(hsp, W_fc, b_fc, out, O);
}